// round 6
// baseline (speedup 1.0000x reference)
#include <cuda_runtime.h>
#include <cuda_bf16.h>
#include <cstdint>

// Problem constants
#define BNUM 8
#define NPTS 8192
#define NPOINTS (BNUM * NPTS)   // 65536
#define TP   32                 // points per block
#define THREADS 512
#define NBLOCKS (NPOINTS / TP)  // 2048
#define OUT_ELEMS ((size_t)NPOINTS * 128)
#define PTS_ELEMS (NPOINTS * 3)

// A staging row stride in u32 words: 512 k-pairs + 1 pad per 8 + 4 extra
// => 580 == 4 (mod 32): A-fragment reads are bank-conflict-free.
#define RSW 580

// Shared memory layout (float words):
//  [0)      s_A[3][32], s_beff[32], s_l2w[512], s_l2b[16], s_l3w[256], s_l3b[16], s_bias[128]  = 1056
//  [1056)   s_idx[32][16] (int)                                                               = 512
//  [1568)   s_wk[32][16][17]  (aliased by s_red[32][128] in the epilogue)                      = 8704
//  [10272)  s_ahi[32][RSW] (u32)                                                              = 18560
//  [28832)  s_alo[32][RSW] (u32)                                                              = 18560
#define OFF_IDX 1056
#define OFF_WK  1568
#define OFF_AHI 10272
#define OFF_ALO 28832
#define SMEM_FLOATS 47392
#define SMEM_BYTES (SMEM_FLOATS * 4)   // 189568 B -> 1 CTA/SM

// Pre-split weight in mma fragment layout: [kt(64)][nt(16)][lane(32)][half(2)] u32
__device__ uint32_t g_whi[65536];
__device__ uint32_t g_wlo[65536];

static __device__ __forceinline__ uint32_t pack2(float x0, float x1) {
    __nv_bfloat162 h = __floats2bfloat162_rn(x0, x1);   // .x = x0 (low half)
    return *reinterpret_cast<uint32_t*>(&h);
}

static __device__ __forceinline__ void mma16816(
    float* d,
    uint32_t a0, uint32_t a1, uint32_t a2, uint32_t a3,
    uint32_t b0, uint32_t b1)
{
    asm volatile(
        "mma.sync.aligned.m16n8k16.row.col.f32.bf16.bf16.f32 "
        "{%0,%1,%2,%3}, {%4,%5,%6,%7}, {%8,%9}, {%0,%1,%2,%3};"
        : "+f"(d[0]), "+f"(d[1]), "+f"(d[2]), "+f"(d[3])
        : "r"(a0), "r"(a1), "r"(a2), "r"(a3), "r"(b0), "r"(b1));
}

// ---------------- weight prep: fp32 [1024][128] -> hi/lo bf16 fragment layout ----------------
__global__ void prep_weight_kernel(const float* __restrict__ w)
{
    int i = blockIdx.x * blockDim.x + threadIdx.x;    // (kt, nt, lane)
    if (i >= 64 * 16 * 32) return;
    const int lane = i & 31;
    const int nt   = (i >> 5) & 15;
    const int kt   = i >> 9;
    const int tk   = lane & 3;
    const int g    = lane >> 2;
    const int n    = nt * 8 + g;
    #pragma unroll
    for (int half = 0; half < 2; half++) {
        const int k0 = kt * 16 + half * 8 + tk * 2;
        const float w0 = w[k0 * 128 + n];
        const float w1 = w[(k0 + 1) * 128 + n];
        const __nv_bfloat16 h0 = __float2bfloat16(w0);
        const __nv_bfloat16 h1 = __float2bfloat16(w1);
        const float l0 = w0 - __bfloat162float(h0);
        const float l1 = w1 - __bfloat162float(h1);
        const int idx = ((kt * 16 + nt) * 32 + lane) * 2 + half;
        g_whi[idx] = pack2(w0, w1);
        g_wlo[idx] = pack2(l0, l1);
    }
}

__global__ void __launch_bounds__(THREADS, 1) ptconv_kernel(
    const float* __restrict__ features,    // [B,N,64]
    const float* __restrict__ input_pts,   // [B,N,3]
    const float* __restrict__ output_pts,  // [B,N,3]
    const int*   __restrict__ indices,     // [B,N,16]
    const float* __restrict__ centers,     // [3,16]
    const float* __restrict__ bias,        // [128]
    const float* __restrict__ l1w,         // [32,48]
    const float* __restrict__ l1b,         // [32]
    const float* __restrict__ l2w,         // [16,32]
    const float* __restrict__ l2b,         // [16]
    const float* __restrict__ l3w,         // [16,16]
    const float* __restrict__ l3b,         // [16]
    float* __restrict__ out)               // [B,N,128]
{
    extern __shared__ float sm[];
    float* s_A    = sm;                 // [3][32]
    float* s_beff = s_A + 96;           // [32]
    float* s_l2w  = s_beff + 32;        // [16][32]
    float* s_l2b  = s_l2w + 512;        // [16]
    float* s_l3w  = s_l2b + 16;         // [16][16]
    float* s_l3b  = s_l3w + 256;        // [16]
    float* s_bias = s_l3b + 16;         // [128]
    int*   s_idx  = (int*)(sm + OFF_IDX);               // [32][16]
    float* s_wk   = sm + OFF_WK;                        // [32][16][17]
    float* s_red  = sm + OFF_WK;                        // alias: [32][128] partials
    uint32_t* s_ahi = (uint32_t*)(sm + OFF_AHI);        // [32][RSW]
    uint32_t* s_alo = (uint32_t*)(sm + OFF_ALO);        // [32][RSW]

    const int tid = threadIdx.x;

    // ---------------- Init: fold centers + l1 into affine form, stage weights ----------------
    if (tid < 32) {
        const int o = tid;
        float be = l1b[o];
        float a[3];
        #pragma unroll
        for (int j = 0; j < 3; j++) {
            float as = 0.f;
            #pragma unroll
            for (int m = 0; m < 16; m++) {
                float wv = l1w[o * 48 + j * 16 + m];
                be -= centers[j * 16 + m] * wv;
                as += wv;
            }
            a[j] = as;
        }
        s_A[0 * 32 + o] = a[0];
        s_A[1 * 32 + o] = a[1];
        s_A[2 * 32 + o] = a[2];
        s_beff[o] = be;
    }
    if (tid < 512 && tid >= 256) { /* spread init */ }
    if (tid < 512) { if (tid < 512) {} }
    for (int i = tid; i < 512; i += THREADS) s_l2w[i] = l2w[i];
    if (tid < 256) s_l3w[tid] = l3w[tid];
    if (tid < 16)  s_l2b[tid] = l2b[tid];
    if (tid < 16)  s_l3b[tid] = l3b[tid];
    if (tid < 128) s_bias[tid] = bias[tid];
    __syncthreads();

    // ---------------- Phase A1: per-(point,neighbor) MLP -> s_wk; resolve indices -> s_idx ----
    {
        const int p  = tid >> 4;                   // 0..31
        const int k  = tid & 15;
        const int pi = blockIdx.x * TP + p;
        const int b  = pi >> 13;                   // N = 8192

        const int idx = indices[pi * 16 + k];
        const int src = (b << 13) + idx;
        s_idx[p * 16 + k] = src;

        const float q0 = input_pts[src * 3 + 0] - output_pts[pi * 3 + 0];
        const float q1 = input_pts[src * 3 + 1] - output_pts[pi * 3 + 1];
        const float q2 = input_pts[src * 3 + 2] - output_pts[pi * 3 + 2];

        float h1[32];
        #pragma unroll
        for (int o = 0; o < 32; o++) {
            float v = s_beff[o] + s_A[o] * q0 + s_A[32 + o] * q1 + s_A[64 + o] * q2;
            h1[o] = fmaxf(v, 0.f);
        }
        float h2[16];
        #pragma unroll
        for (int m = 0; m < 16; m++) {
            float acc = s_l2b[m];
            #pragma unroll
            for (int j = 0; j < 32; j++) acc += h1[j] * s_l2w[m * 32 + j];
            h2[m] = fmaxf(acc, 0.f);
        }
        #pragma unroll
        for (int m = 0; m < 16; m++) {
            float acc = s_l3b[m];
            #pragma unroll
            for (int j = 0; j < 16; j++) acc += h2[j] * s_l3w[m * 16 + j];
            s_wk[(p * 16 + k) * 17 + m] = fmaxf(acc, 0.f);
        }
    }
    __syncthreads();

    // ---------------- Phase B: A[p][k=c*16+m] = sum_kk f[p][kk][c] * wk[p][kk][m] ----------------
    // Features gathered straight from gmem (L2-resident). Thread (pb, ci) owns
    // c in {ci, ci+16, ci+32, ci+48}; accumulate in regs, store hi/lo bf16 pairs.
    {
        const int pb = tid >> 4;
        const int ci = tid & 15;
        float acc[16][4];
        #pragma unroll
        for (int m = 0; m < 16; m++) {
            #pragma unroll
            for (int cc = 0; cc < 4; cc++) acc[m][cc] = 0.f;
        }
        #pragma unroll
        for (int kk = 0; kk < 16; kk++) {
            const int src = s_idx[pb * 16 + kk];
            const float* frow = &features[(size_t)src * 64];
            float fv[4];
            #pragma unroll
            for (int cc = 0; cc < 4; cc++) fv[cc] = frow[ci + 16 * cc];
            const float* wkrow = &s_wk[(pb * 16 + kk) * 17];
            #pragma unroll
            for (int m = 0; m < 16; m++) {
                const float w = wkrow[m];
                #pragma unroll
                for (int cc = 0; cc < 4; cc++) acc[m][cc] += fv[cc] * w;
            }
        }
        #pragma unroll
        for (int cc = 0; cc < 4; cc++) {
            const int c = ci + 16 * cc;
            const int base = pb * RSW + 9 * c;   // word(kp) = kp + kp/8 = 9c + mp
            #pragma unroll
            for (int mp = 0; mp < 8; mp++) {
                const float x0 = acc[2 * mp][cc];
                const float x1 = acc[2 * mp + 1][cc];
                const __nv_bfloat162 h = __floats2bfloat162_rn(x0, x1);
                const float l0 = x0 - __bfloat162float(h.x);
                const float l1 = x1 - __bfloat162float(h.y);
                s_ahi[base + mp] = *reinterpret_cast<const uint32_t*>(&h);
                s_alo[base + mp] = pack2(l0, l1);
            }
        }
    }
    __syncthreads();

    // ---------------- Phase C: tensor-core GEMM  out[32x128] = A[32x1024] @ W[1024x128] ----------
    // 16 warps: kthalf = warp/8 splits the k range; nq = warp%8 gives 2 n-tiles;
    // each warp covers both m-tiles (rows 0-15 and 16-31) reusing its B fragments.
    {
        const int lane = tid & 31;
        const int warp = tid >> 5;
        const int tk = lane & 3;
        const int g  = lane >> 2;
        const int kthalf = warp >> 3;
        const int nq = warp & 7;
        const int nt0 = nq * 2, nt1 = nt0 + 1;

        const uint2* __restrict__ bhi = reinterpret_cast<const uint2*>(g_whi);
        const uint2* __restrict__ blo = reinterpret_cast<const uint2*>(g_wlo);

        float d[2][2][4];   // [mt][nt][frag]
        #pragma unroll
        for (int mt = 0; mt < 2; mt++)
            #pragma unroll
            for (int nn = 0; nn < 2; nn++)
                #pragma unroll
                for (int q = 0; q < 4; q++) d[mt][nn][q] = 0.f;

        const int r0 = g * RSW + tk;
        const int r1 = (g + 8) * RSW + tk;
        const int r2 = (g + 16) * RSW + tk;
        const int r3 = (g + 24) * RSW + tk;

        const int kt0 = kthalf * 32;
        #pragma unroll 2
        for (int kt = kt0; kt < kt0 + 32; kt++) {
            const int ab = kt * 9;
            uint32_t ah[2][4], al[2][4];
            ah[0][0] = s_ahi[r0 + ab];     ah[0][1] = s_ahi[r1 + ab];
            ah[0][2] = s_ahi[r0 + ab + 4]; ah[0][3] = s_ahi[r1 + ab + 4];
            ah[1][0] = s_ahi[r2 + ab];     ah[1][1] = s_ahi[r3 + ab];
            ah[1][2] = s_ahi[r2 + ab + 4]; ah[1][3] = s_ahi[r3 + ab + 4];
            al[0][0] = s_alo[r0 + ab];     al[0][1] = s_alo[r1 + ab];
            al[0][2] = s_alo[r0 + ab + 4]; al[0][3] = s_alo[r1 + ab + 4];
            al[1][0] = s_alo[r2 + ab];     al[1][1] = s_alo[r3 + ab];
            al[1][2] = s_alo[r2 + ab + 4]; al[1][3] = s_alo[r3 + ab + 4];

            const int bbase = (kt * 16) * 32 + lane;
            const uint2 bh0 = bhi[bbase + nt0 * 32];
            const uint2 bh1 = bhi[bbase + nt1 * 32];
            const uint2 bl0 = blo[bbase + nt0 * 32];
            const uint2 bl1 = blo[bbase + nt1 * 32];

            #pragma unroll
            for (int mt = 0; mt < 2; mt++) {
                mma16816(d[mt][0], ah[mt][0], ah[mt][1], ah[mt][2], ah[mt][3], bh0.x, bh0.y);
                mma16816(d[mt][0], ah[mt][0], ah[mt][1], ah[mt][2], ah[mt][3], bl0.x, bl0.y);
                mma16816(d[mt][0], al[mt][0], al[mt][1], al[mt][2], al[mt][3], bh0.x, bh0.y);
                mma16816(d[mt][1], ah[mt][0], ah[mt][1], ah[mt][2], ah[mt][3], bh1.x, bh1.y);
                mma16816(d[mt][1], ah[mt][0], ah[mt][1], ah[mt][2], ah[mt][3], bl1.x, bl1.y);
                mma16816(d[mt][1], al[mt][0], al[mt][1], al[mt][2], al[mt][3], bh1.x, bh1.y);
            }
        }

        __syncthreads();   // all reads of s_wk long done; safe to overwrite with s_red

        // k-half 1 writes partials; k-half 0 accumulates + epilogue.
        if (kthalf == 1) {
            #pragma unroll
            for (int mt = 0; mt < 2; mt++) {
                #pragma unroll
                for (int nn = 0; nn < 2; nn++) {
                    const int col = (nt0 + nn) * 8 + tk * 2;
                    const int p0 = mt * 16 + g;
                    *reinterpret_cast<float2*>(&s_red[p0 * 128 + col]) =
                        make_float2(d[mt][nn][0], d[mt][nn][1]);
                    *reinterpret_cast<float2*>(&s_red[(p0 + 8) * 128 + col]) =
                        make_float2(d[mt][nn][2], d[mt][nn][3]);
                }
            }
        }
        __syncthreads();
        if (kthalf == 0) {
            const float inv = 1.f / 16.f;
            const int pibase = blockIdx.x * TP;
            #pragma unroll
            for (int mt = 0; mt < 2; mt++) {
                #pragma unroll
                for (int nn = 0; nn < 2; nn++) {
                    const int col = (nt0 + nn) * 8 + tk * 2;
                    const float b0 = s_bias[col], b1 = s_bias[col + 1];
                    const int p0 = mt * 16 + g;
                    const float2 r0v = *reinterpret_cast<const float2*>(&s_red[p0 * 128 + col]);
                    const float2 r1v = *reinterpret_cast<const float2*>(&s_red[(p0 + 8) * 128 + col]);
                    *reinterpret_cast<float2*>(&out[(size_t)(pibase + p0) * 128 + col]) =
                        make_float2((d[mt][nn][0] + r0v.x) * inv + b0,
                                    (d[mt][nn][1] + r0v.y) * inv + b1);
                    *reinterpret_cast<float2*>(&out[(size_t)(pibase + p0 + 8) * 128 + col]) =
                        make_float2((d[mt][nn][2] + r1v.x) * inv + b0,
                                    (d[mt][nn][3] + r1v.y) * inv + b1);
                }
            }
        }
    }
}

// Second output of the tuple: output_pts passthrough.
__global__ void copy_pts_kernel(const float* __restrict__ src, float* __restrict__ dst)
{
    const int i = blockIdx.x * blockDim.x + threadIdx.x;
    if (i < PTS_ELEMS) dst[i] = src[i];
}

extern "C" void kernel_launch(void* const* d_in, const int* in_sizes, int n_in,
                              void* d_out, int out_size)
{
    const float* features   = (const float*)d_in[0];
    const float* input_pts  = (const float*)d_in[1];
    const float* output_pts = (const float*)d_in[2];
    const int*   indices    = (const int*)d_in[3];
    const float* centers    = (const float*)d_in[4];
    const float* weight     = (const float*)d_in[5];
    const float* bias       = (const float*)d_in[6];
    const float* l1w        = (const float*)d_in[7];
    const float* l1b        = (const float*)d_in[8];
    const float* l2w        = (const float*)d_in[9];
    const float* l2b        = (const float*)d_in[10];
    const float* l3w        = (const float*)d_in[11];
    const float* l3b        = (const float*)d_in[12];
    float* out = (float*)d_out;

    cudaFuncSetAttribute(ptconv_kernel, cudaFuncAttributeMaxDynamicSharedMemorySize, SMEM_BYTES);

    copy_pts_kernel<<<(PTS_ELEMS + 255) / 256, 256>>>(output_pts, out + OUT_ELEMS);

    prep_weight_kernel<<<(64 * 16 * 32 + 255) / 256, 256>>>(weight);

    ptconv_kernel<<<NBLOCKS, THREADS, SMEM_BYTES>>>(
        features, input_pts, output_pts, indices, centers, bias,
        l1w, l1b, l2w, l2b, l3w, l3b, out);
}

// round 8
// speedup vs baseline: 1.4619x; 1.4619x over previous
#include <cuda_runtime.h>
#include <cuda_bf16.h>
#include <cstdint>

// Problem constants
#define BNUM 8
#define NPTS 8192
#define NPOINTS (BNUM * NPTS)   // 65536
#define TP   32                 // points per block
#define THREADS 256
#define NBLOCKS (NPOINTS / TP)  // 2048
#define OUT_ELEMS ((size_t)NPOINTS * 128)
#define PTS_ELEMS (NPOINTS * 3)

// Per-point row slot (u32 words). Holds fp32 features [16][64]=1024 words during
// gather/Phase-B, then bf16 A: hi pairs at [0,580), lo pairs at [580,1160).
// 1188 % 32 == 4  -> Phase-C A-fragment LDS reads are bank-conflict-free.
#define SLOT 1188
#define HILO 580

// Shared memory layout (float words):
//  [0)      s_A[96], s_beff[32], s_l2w[512], s_l2b[16], s_l3w[256], s_l3b[16], s_bias[128] = 1056
//  [1056)   mbarrier (2 words) + pad                                                      = 8
//  [1064)   s_wk[32][16][17]                                                              = 8704
//  [9768)   pad to 16B                                                                    = 0 (9768*4 % 16 == 0? 39072/16=2442 ok)
//  [9768)   region: 32 slots x 1188                                                       = 38016
#define OFF_MBAR 1056
#define OFF_WK   1064
#define OFF_REG  9768
#define SMEM_FLOATS (OFF_REG + 32 * SLOT)     // 47784
#define SMEM_BYTES (SMEM_FLOATS * 4)          // 191136 B -> 1 CTA/SM

// Pre-split weight in mma fragment layout: [kt(64)][nt(16)][lane(32)][half(2)] u32
__device__ uint32_t g_whi[65536];
__device__ uint32_t g_wlo[65536];

static __device__ __forceinline__ uint32_t pack2(float x0, float x1) {
    __nv_bfloat162 h = __floats2bfloat162_rn(x0, x1);   // .x = x0 (low half)
    return *reinterpret_cast<uint32_t*>(&h);
}

static __device__ __forceinline__ uint32_t smem_u32(const void* p) {
    uint32_t a;
    asm("{ .reg .u64 t; cvta.to.shared.u64 t, %1; cvt.u32.u64 %0, t; }" : "=r"(a) : "l"(p));
    return a;
}

static __device__ __forceinline__ void mma16816(
    float* d,
    uint32_t a0, uint32_t a1, uint32_t a2, uint32_t a3,
    uint32_t b0, uint32_t b1)
{
    asm volatile(
        "mma.sync.aligned.m16n8k16.row.col.f32.bf16.bf16.f32 "
        "{%0,%1,%2,%3}, {%4,%5,%6,%7}, {%8,%9}, {%0,%1,%2,%3};"
        : "+f"(d[0]), "+f"(d[1]), "+f"(d[2]), "+f"(d[3])
        : "r"(a0), "r"(a1), "r"(a2), "r"(a3), "r"(b0), "r"(b1));
}

// ---------------- weight prep: fp32 [1024][128] -> hi/lo bf16 fragment layout ----------------
__global__ void prep_weight_kernel(const float* __restrict__ w)
{
    int i = blockIdx.x * blockDim.x + threadIdx.x;    // (kt, nt, lane)
    if (i >= 64 * 16 * 32) return;
    const int lane = i & 31;
    const int nt   = (i >> 5) & 15;
    const int kt   = i >> 9;
    const int tk   = lane & 3;
    const int g    = lane >> 2;
    const int n    = nt * 8 + g;
    #pragma unroll
    for (int half = 0; half < 2; half++) {
        const int k0 = kt * 16 + half * 8 + tk * 2;
        const float w0 = w[k0 * 128 + n];
        const float w1 = w[(k0 + 1) * 128 + n];
        const __nv_bfloat16 h0 = __float2bfloat16(w0);
        const __nv_bfloat16 h1 = __float2bfloat16(w1);
        const float l0 = w0 - __bfloat162float(h0);
        const float l1 = w1 - __bfloat162float(h1);
        const int idx = ((kt * 16 + nt) * 32 + lane) * 2 + half;
        g_whi[idx] = pack2(w0, w1);
        g_wlo[idx] = pack2(l0, l1);
    }
}

__global__ void __launch_bounds__(THREADS, 1) ptconv_kernel(
    const float* __restrict__ features,    // [B,N,64]
    const float* __restrict__ input_pts,   // [B,N,3]
    const float* __restrict__ output_pts,  // [B,N,3]
    const int*   __restrict__ indices,     // [B,N,16]
    const float* __restrict__ centers,     // [3,16]
    const float* __restrict__ bias,        // [128]
    const float* __restrict__ l1w,         // [32,48]
    const float* __restrict__ l1b,         // [32]
    const float* __restrict__ l2w,         // [16,32]
    const float* __restrict__ l2b,         // [16]
    const float* __restrict__ l3w,         // [16,16]
    const float* __restrict__ l3b,         // [16]
    float* __restrict__ out)               // [B,N,128]
{
    extern __shared__ float sm[];
    float* s_A    = sm;                 // [3][32]
    float* s_beff = s_A + 96;           // [32]
    float* s_l2w  = s_beff + 32;        // [16][32]
    float* s_l2b  = s_l2w + 512;        // [16]
    float* s_l3w  = s_l2b + 16;         // [16][16]
    float* s_l3b  = s_l3w + 256;        // [16]
    float* s_bias = s_l3b + 16;         // [128]
    float* s_wk   = sm + OFF_WK;        // [32][16][17]
    uint32_t* s_reg = (uint32_t*)(sm + OFF_REG);   // 32 slots x SLOT

    const int tid = threadIdx.x;
    const uint32_t mbar = smem_u32(sm + OFF_MBAR);
    const uint32_t reg_base = smem_u32(sm + OFF_REG);

    // ---------------- mbarrier init + expect (one phase, 512 * 256B = 131072B) ----------------
    if (tid == 0) {
        asm volatile("mbarrier.init.shared.b64 [%0], 1;" :: "r"(mbar) : "memory");
        asm volatile("mbarrier.arrive.expect_tx.shared.b64 _, [%0], %1;"
                     :: "r"(mbar), "r"(131072) : "memory");
    }
    __syncthreads();

    // ---------------- Issue feature-row bulk copies; stash relative coords ----------------
    float q[2][3];
    #pragma unroll
    for (int it = 0; it < 2; it++) {
        const int e = tid + 256 * it;
        const int p = e >> 4;
        const int k = e & 15;
        const int pi = blockIdx.x * TP + p;
        const int b  = pi >> 13;                   // N = 8192
        const int idx = indices[pi * 16 + k];
        const int src = (b << 13) + idx;

        q[it][0] = input_pts[src * 3 + 0] - output_pts[pi * 3 + 0];
        q[it][1] = input_pts[src * 3 + 1] - output_pts[pi * 3 + 1];
        q[it][2] = input_pts[src * 3 + 2] - output_pts[pi * 3 + 2];

        const uint32_t dst = reg_base + (uint32_t)(p * SLOT + k * 64) * 4u;
        const float* srcp = features + (size_t)src * 64;
        asm volatile(
            "cp.async.bulk.shared::cta.global.mbarrier::complete_tx::bytes "
            "[%0], [%1], %2, [%3];"
            :: "r"(dst), "l"(srcp), "r"(256), "r"(mbar) : "memory");
    }

    // ---------------- Stage small weights (overlaps with bulk copies) ----------------
    if (tid < 32) {
        const int o = tid;
        float be = l1b[o];
        float a[3];
        #pragma unroll
        for (int j = 0; j < 3; j++) {
            float as = 0.f;
            #pragma unroll
            for (int m = 0; m < 16; m++) {
                float wv = l1w[o * 48 + j * 16 + m];
                be -= centers[j * 16 + m] * wv;
                as += wv;
            }
            a[j] = as;
        }
        s_A[0 * 32 + o] = a[0];
        s_A[1 * 32 + o] = a[1];
        s_A[2 * 32 + o] = a[2];
        s_beff[o] = be;
    }
    for (int i = tid; i < 512; i += THREADS) s_l2w[i] = l2w[i];
    if (tid < 256) s_l3w[tid] = l3w[tid];
    if (tid < 16)  s_l2b[tid] = l2b[tid];
    if (tid < 16)  s_l3b[tid] = l3b[tid];
    if (tid < 128) s_bias[tid] = bias[tid];
    __syncthreads();

    // ---------------- Phase A1: MLP for 2 (p,k) pairs per thread -> s_wk ----------------
    #pragma unroll
    for (int it = 0; it < 2; it++) {
        const int e = tid + 256 * it;
        const int p = e >> 4;
        const int k = e & 15;
        float h1[32];
        #pragma unroll
        for (int o = 0; o < 32; o++) {
            float v = s_beff[o] + s_A[o] * q[it][0] + s_A[32 + o] * q[it][1] + s_A[64 + o] * q[it][2];
            h1[o] = fmaxf(v, 0.f);
        }
        float h2[16];
        #pragma unroll
        for (int m = 0; m < 16; m++) {
            float acc = s_l2b[m];
            #pragma unroll
            for (int j = 0; j < 32; j++) acc += h1[j] * s_l2w[m * 32 + j];
            h2[m] = fmaxf(acc, 0.f);
        }
        #pragma unroll
        for (int m = 0; m < 16; m++) {
            float acc = s_l3b[m];
            #pragma unroll
            for (int j = 0; j < 16; j++) acc += h2[j] * s_l3w[m * 16 + j];
            s_wk[(p * 16 + k) * 17 + m] = fmaxf(acc, 0.f);
        }
    }

    // ---------------- Wait for feature copies; sync for s_wk visibility ----------------
    {
        uint32_t done;
        asm volatile(
            "{\n\t.reg .pred p;\n\t"
            "mbarrier.try_wait.parity.acquire.cta.shared::cta.b64 p, [%1], 0;\n\t"
            "selp.b32 %0, 1, 0, p;\n\t}"
            : "=r"(done) : "r"(mbar) : "memory");
        while (!done) {
            asm volatile(
                "{\n\t.reg .pred p;\n\t"
                "mbarrier.try_wait.parity.acquire.cta.shared::cta.b64 p, [%1], 0, 0x989680;\n\t"
                "selp.b32 %0, 1, 0, p;\n\t}"
                : "=r"(done) : "r"(mbar) : "memory");
        }
    }
    __syncthreads();

    // ---------------- Phase B: two passes of 16 points; regs -> bf16 hi/lo into slots ----------
    // Thread (pb, ci) owns c in {4ci..4ci+3} via one LDS.128 per neighbor row.
    #pragma unroll
    for (int pass = 0; pass < 2; pass++) {
        const int pb = (tid >> 4) + 16 * pass;
        const int ci = tid & 15;
        float acc[16][4];
        #pragma unroll
        for (int m = 0; m < 16; m++)
            #pragma unroll
            for (int cc = 0; cc < 4; cc++) acc[m][cc] = 0.f;

        #pragma unroll
        for (int kk = 0; kk < 16; kk++) {
            const float4 fv = *reinterpret_cast<const float4*>(
                &s_reg[pb * SLOT + kk * 64 + ci * 4]);
            const float* wkrow = &s_wk[(pb * 16 + kk) * 17];
            #pragma unroll
            for (int m = 0; m < 16; m++) {
                const float w = wkrow[m];
                acc[m][0] += fv.x * w;
                acc[m][1] += fv.y * w;
                acc[m][2] += fv.z * w;
                acc[m][3] += fv.w * w;
            }
        }
        __syncthreads();   // all reads of this pass's fp32 rows complete
        #pragma unroll
        for (int cc = 0; cc < 4; cc++) {
            const int c = ci * 4 + cc;
            const int base = pb * SLOT + 9 * c;   // hi word; lo at +HILO
            #pragma unroll
            for (int mp = 0; mp < 8; mp++) {
                const float x0 = acc[2 * mp][cc];
                const float x1 = acc[2 * mp + 1][cc];
                const __nv_bfloat162 h = __floats2bfloat162_rn(x0, x1);
                const float l0 = x0 - __bfloat162float(h.x);
                const float l1 = x1 - __bfloat162float(h.y);
                s_reg[base + mp] = *reinterpret_cast<const uint32_t*>(&h);
                s_reg[base + HILO + mp] = pack2(l0, l1);
            }
        }
    }
    __syncthreads();

    // ---------------- Phase C: out[32x128] = A[32x1024] @ W[1024x128], 8 warps ----------------
    // warp = n-quad (2 n-tiles), covers both m-tiles, full k: every B fragment
    // loaded exactly once per 32-point block.
    {
        const int lane = tid & 31;
        const int warp = tid >> 5;
        const int tk = lane & 3;
        const int g  = lane >> 2;
        const int nt0 = warp * 2, nt1 = nt0 + 1;

        const uint2* __restrict__ bhi = reinterpret_cast<const uint2*>(g_whi);
        const uint2* __restrict__ blo = reinterpret_cast<const uint2*>(g_wlo);

        float d[2][2][4];   // [mt][nt][frag]
        #pragma unroll
        for (int mt = 0; mt < 2; mt++)
            #pragma unroll
            for (int nn = 0; nn < 2; nn++)
                #pragma unroll
                for (int qq = 0; qq < 4; qq++) d[mt][nn][qq] = 0.f;

        const int r0 = g * SLOT + tk;
        const int r1 = (g + 8) * SLOT + tk;
        const int r2 = (g + 16) * SLOT + tk;
        const int r3 = (g + 24) * SLOT + tk;

        #pragma unroll 4
        for (int kt = 0; kt < 64; kt++) {
            const int ab = kt * 9;
            uint32_t ah[2][4], al[2][4];
            ah[0][0] = s_reg[r0 + ab];            ah[0][1] = s_reg[r1 + ab];
            ah[0][2] = s_reg[r0 + ab + 4];        ah[0][3] = s_reg[r1 + ab + 4];
            ah[1][0] = s_reg[r2 + ab];            ah[1][1] = s_reg[r3 + ab];
            ah[1][2] = s_reg[r2 + ab + 4];        ah[1][3] = s_reg[r3 + ab + 4];
            al[0][0] = s_reg[r0 + ab + HILO];     al[0][1] = s_reg[r1 + ab + HILO];
            al[0][2] = s_reg[r0 + ab + HILO + 4]; al[0][3] = s_reg[r1 + ab + HILO + 4];
            al[1][0] = s_reg[r2 + ab + HILO];     al[1][1] = s_reg[r3 + ab + HILO];
            al[1][2] = s_reg[r2 + ab + HILO + 4]; al[1][3] = s_reg[r3 + ab + HILO + 4];

            const int bbase = (kt * 16) * 32 + lane;
            const uint2 bh0 = bhi[bbase + nt0 * 32];
            const uint2 bh1 = bhi[bbase + nt1 * 32];
            const uint2 bl0 = blo[bbase + nt0 * 32];
            const uint2 bl1 = blo[bbase + nt1 * 32];

            #pragma unroll
            for (int mt = 0; mt < 2; mt++) {
                mma16816(d[mt][0], ah[mt][0], ah[mt][1], ah[mt][2], ah[mt][3], bh0.x, bh0.y);
                mma16816(d[mt][0], ah[mt][0], ah[mt][1], ah[mt][2], ah[mt][3], bl0.x, bl0.y);
                mma16816(d[mt][0], al[mt][0], al[mt][1], al[mt][2], al[mt][3], bh0.x, bh0.y);
                mma16816(d[mt][1], ah[mt][0], ah[mt][1], ah[mt][2], ah[mt][3], bh1.x, bh1.y);
                mma16816(d[mt][1], ah[mt][0], ah[mt][1], ah[mt][2], ah[mt][3], bl1.x, bl1.y);
                mma16816(d[mt][1], al[mt][0], al[mt][1], al[mt][2], al[mt][3], bh1.x, bh1.y);
            }
        }

        const float inv = 1.f / 16.f;
        const int pibase = blockIdx.x * TP;
        #pragma unroll
        for (int mt = 0; mt < 2; mt++) {
            #pragma unroll
            for (int nn = 0; nn < 2; nn++) {
                const int col = (nt0 + nn) * 8 + tk * 2;
                const float b0 = s_bias[col], b1 = s_bias[col + 1];
                const int p0 = mt * 16 + g;
                *reinterpret_cast<float2*>(&out[(size_t)(pibase + p0) * 128 + col]) =
                    make_float2(d[mt][nn][0] * inv + b0, d[mt][nn][1] * inv + b1);
                *reinterpret_cast<float2*>(&out[(size_t)(pibase + p0 + 8) * 128 + col]) =
                    make_float2(d[mt][nn][2] * inv + b0, d[mt][nn][3] * inv + b1);
            }
        }
    }
}

// Second output of the tuple: output_pts passthrough.
__global__ void copy_pts_kernel(const float* __restrict__ src, float* __restrict__ dst)
{
    const int i = blockIdx.x * blockDim.x + threadIdx.x;
    if (i < PTS_ELEMS) dst[i] = src[i];
}

extern "C" void kernel_launch(void* const* d_in, const int* in_sizes, int n_in,
                              void* d_out, int out_size)
{
    const float* features   = (const float*)d_in[0];
    const float* input_pts  = (const float*)d_in[1];
    const float* output_pts = (const float*)d_in[2];
    const int*   indices    = (const int*)d_in[3];
    const float* centers    = (const float*)d_in[4];
    const float* weight     = (const float*)d_in[5];
    const float* bias       = (const float*)d_in[6];
    const float* l1w        = (const float*)d_in[7];
    const float* l1b        = (const float*)d_in[8];
    const float* l2w        = (const float*)d_in[9];
    const float* l2b        = (const float*)d_in[10];
    const float* l3w        = (const float*)d_in[11];
    const float* l3b        = (const float*)d_in[12];
    float* out = (float*)d_out;

    cudaFuncSetAttribute(ptconv_kernel, cudaFuncAttributeMaxDynamicSharedMemorySize, SMEM_BYTES);

    copy_pts_kernel<<<(PTS_ELEMS + 255) / 256, 256>>>(output_pts, out + OUT_ELEMS);

    prep_weight_kernel<<<(64 * 16 * 32 + 255) / 256, 256>>>(weight);

    ptconv_kernel<<<NBLOCKS, THREADS, SMEM_BYTES>>>(
        features, input_pts, output_pts, indices, centers, bias,
        l1w, l1b, l2w, l2b, l3w, l3b, out);
}